// round 5
// baseline (speedup 1.0000x reference)
#include <cuda_runtime.h>

// LightGCN propagation, gather-formulation (no atomics in the hot path):
//   e0 = concat(user_emb, item_emb)            (N = 300000, D = 64)
//   e_{l+1}[r] = sum_{edges e: rows[e]==r} vals[e] * e_l[cols[e]]
//   out = (e0 + e1 + e2 + e3) / 4
//
// Per launch: bucket edges into a padded CSR (one atomic-cursor pass), then
// 3 gather-only SpMM layers (one warp per row, register accumulation, single
// store per row — no pre-zeroing, no RMW atomics), then one fused final pass.

#define DIM      64
#define DIM4     16
#define PAD_W    64              // padded CSR width (deg ~ Poisson(13.3))
#define NMAX     300000
#define OVF_CAP  4096
#define TPB      256

// ---- static scratch (alloc-free rule) -------------------------------------
__device__ int   g_cnt[NMAX];                       // per-row degree / cursor
__device__ uint2 g_list[(size_t)NMAX * PAD_W];      // {col, val_bits}  153.6MB
__device__ int   g_ovf_cnt;
__device__ int4  g_ovf[OVF_CAP];                    // {row, col, val_bits, 0}
__device__ float g_bufB[(size_t)NMAX * DIM];        // layer-1 output
__device__ float g_bufC[(size_t)NMAX * DIM];        // layer-2 output

// ---- zero counters --------------------------------------------------------
__global__ void lg_zero(int n_rows) {
    int i = blockIdx.x * blockDim.x + threadIdx.x;
    if (i < n_rows) g_cnt[i] = 0;
    if (i == 0) g_ovf_cnt = 0;
}

// ---- bucket edges into padded CSR -----------------------------------------
__global__ void lg_build(const int* __restrict__ rows,
                         const int* __restrict__ cols,
                         const float* __restrict__ vals, int nnz) {
    int e = blockIdx.x * blockDim.x + threadIdx.x;
    if (e >= nnz) return;
    int   r = rows[e];
    int   c = cols[e];
    float v = vals[e];
    int pos = atomicAdd(&g_cnt[r], 1);
    if (pos < PAD_W) {
        g_list[(size_t)r * PAD_W + pos] = make_uint2((unsigned)c, __float_as_uint(v));
    } else {
        int o = atomicAdd(&g_ovf_cnt, 1);
        if (o < OVF_CAP) g_ovf[o] = make_int4(r, c, __float_as_int(v), 0);
    }
}

// ---- gather SpMM: one warp per row, lane owns 2 floats of the 64-dim row --
// in = (col < n0) ? in0[col] : in1[col - n0]   (lets layer 1 read raw inputs)
__global__ void lg_gather(const float* __restrict__ in0,
                          const float* __restrict__ in1, int n0,
                          float* __restrict__ out, int n_rows) {
    int warp = (int)((blockIdx.x * (unsigned)blockDim.x + threadIdx.x) >> 5);
    int lane = threadIdx.x & 31;
    if (warp >= n_rows) return;

    int deg = g_cnt[warp];
    if (deg > PAD_W) deg = PAD_W;

    float2 acc = make_float2(0.f, 0.f);
    const size_t base = (size_t)warp * PAD_W;

    for (int start = 0; start < deg; start += 32) {
        int nb = min(32, deg - start);
        uint2 ent = (lane < nb) ? g_list[base + start + lane] : make_uint2(0u, 0u);
        #pragma unroll 4
        for (int j = 0; j < nb; j++) {
            int   c = __shfl_sync(0xffffffff, (int)ent.x, j);
            float v = __uint_as_float(__shfl_sync(0xffffffff, ent.y, j));
            const float* src = (c < n0) ? in0 + (size_t)c * DIM
                                        : in1 + (size_t)(c - n0) * DIM;
            float2 x = *reinterpret_cast<const float2*>(src + 2 * lane);
            acc.x += v * x.x;
            acc.y += v * x.y;
        }
    }
    *reinterpret_cast<float2*>(out + (size_t)warp * DIM + 2 * lane) = acc;
}

// ---- overflow fixup: atomic-add the (expected zero) spilled edges ---------
__global__ void lg_ovf_fix(const float* __restrict__ in0,
                           const float* __restrict__ in1, int n0,
                           float* __restrict__ out) {
    int t = blockIdx.x * blockDim.x + threadIdx.x;
    int e = t >> 4, part = t & 15;
    int n = g_ovf_cnt; if (n > OVF_CAP) n = OVF_CAP;
    if (e >= n) return;
    int4 rec = g_ovf[e];
    const float* src = (rec.y < n0) ? in0 + (size_t)rec.y * DIM
                                    : in1 + (size_t)(rec.y - n0) * DIM;
    float v = __int_as_float(rec.z);
    float4 x = *reinterpret_cast<const float4*>(src + part * 4);
    float* dst = out + (size_t)rec.x * DIM + part * 4;
    asm volatile("red.global.add.v4.f32 [%0], {%1, %2, %3, %4};"
                 :: "l"(dst), "f"(v * x.x), "f"(v * x.y),
                    "f"(v * x.z), "f"(v * x.w) : "memory");
}

// ---- final: out = (concat(user,item) + B + C + out) * 0.25 ----------------
__global__ void lg_final(const float4* __restrict__ user,
                         const float4* __restrict__ item, int n_user4,
                         const float4* __restrict__ B,
                         const float4* __restrict__ C,
                         float4* __restrict__ out, int n4) {
    int i = blockIdx.x * blockDim.x + threadIdx.x;
    if (i >= n4) return;
    float4 e0 = (i < n_user4) ? user[i] : item[i - n_user4];
    float4 b = B[i], c = C[i], o = out[i];
    out[i] = make_float4((e0.x + b.x + c.x + o.x) * 0.25f,
                         (e0.y + b.y + c.y + o.y) * 0.25f,
                         (e0.z + b.z + c.z + o.z) * 0.25f,
                         (e0.w + b.w + c.w + o.w) * 0.25f);
}

extern "C" void kernel_launch(void* const* d_in, const int* in_sizes, int n_in,
                              void* d_out, int out_size) {
    const float* user = (const float*)d_in[0];
    const float* item = (const float*)d_in[1];
    const float* vals = (const float*)d_in[2];
    const int*   rows = (const int*)d_in[3];
    const int*   cols = (const int*)d_in[4];

    int n_user  = in_sizes[0] / DIM;
    int n_item  = in_sizes[1] / DIM;
    int nnz     = in_sizes[2];
    int n_total = n_user + n_item;
    int n4      = n_total * DIM4;
    int n_user4 = n_user * DIM4;

    float* out = (float*)d_out;

    float* bufB; float* bufC;
    cudaGetSymbolAddress((void**)&bufB, g_bufB);
    cudaGetSymbolAddress((void**)&bufC, g_bufC);

    int zero_blocks   = (n_total + TPB - 1) / TPB;
    int build_blocks  = (nnz + TPB - 1) / TPB;
    int gather_blocks = (n_total * 32 + TPB - 1) / TPB;   // 1 warp per row
    int ew_blocks     = (n4 + TPB - 1) / TPB;
    int ovf_blocks    = (OVF_CAP * DIM4 + TPB - 1) / TPB;

    // build padded CSR
    lg_zero<<<zero_blocks, TPB>>>(n_total);
    lg_build<<<build_blocks, TPB>>>(rows, cols, vals, nnz);

    // layer 1: raw inputs -> B
    lg_gather<<<gather_blocks, TPB>>>(user, item, n_user, bufB, n_total);
    lg_ovf_fix<<<ovf_blocks, TPB>>>(user, item, n_user, bufB);

    // layer 2: B -> C
    lg_gather<<<gather_blocks, TPB>>>(bufB, bufB, n_total, bufC, n_total);
    lg_ovf_fix<<<ovf_blocks, TPB>>>(bufB, bufB, n_total, bufC);

    // layer 3: C -> d_out
    lg_gather<<<gather_blocks, TPB>>>(bufC, bufC, n_total, out, n_total);
    lg_ovf_fix<<<ovf_blocks, TPB>>>(bufC, bufC, n_total, out);

    // out = (e0 + e1 + e2 + e3) / 4
    lg_final<<<ew_blocks, TPB>>>((const float4*)user, (const float4*)item,
                                 n_user4, (const float4*)bufB,
                                 (const float4*)bufC, (float4*)out, n4);
}

// round 6
// speedup vs baseline: 1.2225x; 1.2225x over previous
#include <cuda_runtime.h>
#include <cuda_fp16.h>

// LightGCN propagation, gather formulation with fp16 intermediate embeddings:
//   e0 = concat(user_emb, item_emb)           (N = 300000, D = 64)
//   e_{l+1}[r] = sum_{edges e: rows[e]==r} vals[e] * e_l[cols[e]]
//   out = (e0 + e1 + e2 + e3) / 4
//
// Intermediate layers stored as half (row = 128B = one L2 sector per edge
// gather). Accumulation is fp32 in registers; e0 enters the final sum in
// fp32. Final mean fused into the layer-3 gather.

#define DIM      64
#define DIM2     32              // half2 per row
#define PAD_W    64              // padded CSR width (deg ~ Poisson(13.3))
#define NMAX     300000
#define OVF_CAP  4096
#define TPB      256

// ---- static scratch (alloc-free rule) -------------------------------------
__device__ int     g_cnt[NMAX];                       // per-row degree/cursor
__device__ uint2   g_list[(size_t)NMAX * PAD_W];      // {col, val_bits}
__device__ int     g_ovf_cnt;
__device__ int4    g_ovf[OVF_CAP];                    // {row, col, val_bits, 0}
__device__ __half2 g_h0[(size_t)NMAX * DIM2];         // e0 (half)
__device__ __half2 g_h1[(size_t)NMAX * DIM2];         // e1 (half)
__device__ __half2 g_h2[(size_t)NMAX * DIM2];         // e2 (half)

// ---- fused: zero counters + convert e0 -> half ----------------------------
__global__ void lg_prep(const float2* __restrict__ user,
                        const float2* __restrict__ item,
                        int n_user2, int n2, int n_rows) {
    int i = blockIdx.x * blockDim.x + threadIdx.x;
    if (i < n_rows) g_cnt[i] = 0;
    if (i == 0) g_ovf_cnt = 0;
    if (i >= n2) return;
    float2 v = (i < n_user2) ? user[i] : item[i - n_user2];
    g_h0[i] = __float22half2_rn(v);
}

// ---- bucket edges into padded CSR -----------------------------------------
__global__ void lg_build(const int* __restrict__ rows,
                         const int* __restrict__ cols,
                         const float* __restrict__ vals, int nnz) {
    int e = blockIdx.x * blockDim.x + threadIdx.x;
    if (e >= nnz) return;
    int   r = rows[e];
    int   c = cols[e];
    float v = vals[e];
    int pos = atomicAdd(&g_cnt[r], 1);
    if (pos < PAD_W) {
        g_list[(size_t)r * PAD_W + pos] = make_uint2((unsigned)c, __float_as_uint(v));
    } else {
        int o = atomicAdd(&g_ovf_cnt, 1);
        if (o < OVF_CAP) g_ovf[o] = make_int4(r, c, __float_as_int(v), 0);
    }
}

// ---- core per-row gather: fp32 accumulate from half source ----------------
__device__ __forceinline__ float2 row_gather(const __half2* __restrict__ src,
                                             int row, int lane) {
    int deg = g_cnt[row];
    if (deg > PAD_W) deg = PAD_W;
    float2 acc = make_float2(0.f, 0.f);
    const size_t base = (size_t)row * PAD_W;
    for (int start = 0; start < deg; start += 32) {
        int nb = min(32, deg - start);
        uint2 ent = (lane < nb) ? g_list[base + start + lane] : make_uint2(0u, 0u);
        #pragma unroll 4
        for (int j = 0; j < nb; j++) {
            int   c = __shfl_sync(0xffffffff, (int)ent.x, j);
            float v = __uint_as_float(__shfl_sync(0xffffffff, ent.y, j));
            float2 x = __half22float2(src[(size_t)c * DIM2 + lane]);
            acc.x += v * x.x;
            acc.y += v * x.y;
        }
    }
    return acc;
}

// ---- gather SpMM into a half buffer ---------------------------------------
__global__ void lg_gather_h(const __half2* __restrict__ src,
                            __half2* __restrict__ dst, int n_rows) {
    int warp = (int)((blockIdx.x * (unsigned)blockDim.x + threadIdx.x) >> 5);
    int lane = threadIdx.x & 31;
    if (warp >= n_rows) return;
    float2 acc = row_gather(src, warp, lane);
    dst[(size_t)warp * DIM2 + lane] = __float22half2_rn(acc);
}

// ---- layer-3 gather fused with the final mean -----------------------------
__global__ void lg_gather_final(const __half2* __restrict__ src,   // e2
                                const float* __restrict__ user,
                                const float* __restrict__ item, int n_user,
                                const __half2* __restrict__ e1,
                                const __half2* __restrict__ e2,
                                float* __restrict__ out, int n_rows) {
    int warp = (int)((blockIdx.x * (unsigned)blockDim.x + threadIdx.x) >> 5);
    int lane = threadIdx.x & 31;
    if (warp >= n_rows) return;
    float2 acc = row_gather(src, warp, lane);             // e3 (fp32 regs)

    const float* b0 = (warp < n_user) ? user + (size_t)warp * DIM
                                      : item + (size_t)(warp - n_user) * DIM;
    float2 v0 = *reinterpret_cast<const float2*>(b0 + 2 * lane);
    float2 v1 = __half22float2(e1[(size_t)warp * DIM2 + lane]);
    float2 v2 = __half22float2(e2[(size_t)warp * DIM2 + lane]);

    float2 r;
    r.x = (v0.x + v1.x + v2.x + acc.x) * 0.25f;
    r.y = (v0.y + v1.y + v2.y + acc.y) * 0.25f;
    *reinterpret_cast<float2*>(out + (size_t)warp * DIM + 2 * lane) = r;
}

// ---- overflow fixup into a half buffer (expected count: 0) ----------------
__global__ void lg_ovf_fix_h(const __half2* __restrict__ src,
                             __half2* __restrict__ dst) {
    int n = g_ovf_cnt; if (n > OVF_CAP) n = OVF_CAP;
    int total = n * 32;
    for (int t = blockIdx.x * blockDim.x + threadIdx.x; t < total;
         t += gridDim.x * blockDim.x) {
        int e = t >> 5, lane = t & 31;
        int4 rec = g_ovf[e];
        float v = __int_as_float(rec.z);
        float2 x = __half22float2(src[(size_t)rec.y * DIM2 + lane]);
        atomicAdd(&dst[(size_t)rec.x * DIM2 + lane],
                  __float22half2_rn(make_float2(v * x.x, v * x.y)));
    }
}

// ---- overflow fixup into fp32 out with 0.25 scale (layer 3) ---------------
__global__ void lg_ovf_fix_f(const __half2* __restrict__ src,
                             float* __restrict__ out) {
    int n = g_ovf_cnt; if (n > OVF_CAP) n = OVF_CAP;
    int total = n * 32;
    for (int t = blockIdx.x * blockDim.x + threadIdx.x; t < total;
         t += gridDim.x * blockDim.x) {
        int e = t >> 5, lane = t & 31;
        int4 rec = g_ovf[e];
        float v = 0.25f * __int_as_float(rec.z);
        float2 x = __half22float2(src[(size_t)rec.y * DIM2 + lane]);
        atomicAdd(out + (size_t)rec.x * DIM + 2 * lane,     v * x.x);
        atomicAdd(out + (size_t)rec.x * DIM + 2 * lane + 1, v * x.y);
    }
}

extern "C" void kernel_launch(void* const* d_in, const int* in_sizes, int n_in,
                              void* d_out, int out_size) {
    const float* user = (const float*)d_in[0];
    const float* item = (const float*)d_in[1];
    const float* vals = (const float*)d_in[2];
    const int*   rows = (const int*)d_in[3];
    const int*   cols = (const int*)d_in[4];

    int n_user  = in_sizes[0] / DIM;
    int n_item  = in_sizes[1] / DIM;
    int nnz     = in_sizes[2];
    int n_total = n_user + n_item;
    int n2      = n_total * DIM2;        // half2 count over full table
    int n_user2 = n_user * DIM2;

    float* out = (float*)d_out;

    __half2* h0; __half2* h1; __half2* h2;
    cudaGetSymbolAddress((void**)&h0, g_h0);
    cudaGetSymbolAddress((void**)&h1, g_h1);
    cudaGetSymbolAddress((void**)&h2, g_h2);

    int prep_blocks   = (n2 + TPB - 1) / TPB;
    int build_blocks  = (nnz + TPB - 1) / TPB;
    int gather_blocks = (n_total * 32 + TPB - 1) / TPB;   // 1 warp per row
    int ovf_blocks    = 32;                               // grid-stride stub

    // prep: zero counters + e0 -> half
    lg_prep<<<prep_blocks, TPB>>>((const float2*)user, (const float2*)item,
                                  n_user2, n2, n_total);
    lg_build<<<build_blocks, TPB>>>(rows, cols, vals, nnz);

    // layer 1: h0 -> h1
    lg_gather_h<<<gather_blocks, TPB>>>(h0, h1, n_total);
    lg_ovf_fix_h<<<ovf_blocks, TPB>>>(h0, h1);

    // layer 2: h1 -> h2
    lg_gather_h<<<gather_blocks, TPB>>>(h1, h2, n_total);
    lg_ovf_fix_h<<<ovf_blocks, TPB>>>(h1, h2);

    // layer 3 + final mean: out = (e0 + e1 + e2 + S*e2) / 4
    lg_gather_final<<<gather_blocks, TPB>>>(h2, user, item, n_user,
                                            h1, h2, out, n_total);
    lg_ovf_fix_f<<<ovf_blocks, TPB>>>(h2, out);
}